// round 5
// baseline (speedup 1.0000x reference)
#include <cuda_runtime.h>

#define NB   2
#define NN   512
#define DDIM 128
#define HH   8

// ---------------------------------------------------------------------------
// Scratch (device globals — no allocation allowed)
// ---------------------------------------------------------------------------
__device__ __align__(128) float g_qkv [NB*NN*384];          // Q at [tok][0..128), K at [128..256)
__device__ __align__(128) float g_vt  [NB*HH*16*NN];        // V transposed: [b][h][dk][m]
__device__ __align__(128) float g_Ebuf[(size_t)NB*NN*NN*HH];// scores then _E, layout [b][n][m][h]
__device__ __align__(128) float g_gsum[NB*HH*NN];           // sum_m sigmoid(G)

// ---------------------------------------------------------------------------
// Helpers: packed f32x2 (Blackwell dual FP32) + cp.async
// ---------------------------------------------------------------------------
__device__ __forceinline__ unsigned long long fma2(unsigned long long a,
                                                   unsigned long long b,
                                                   unsigned long long c) {
    unsigned long long d;
    asm("fma.rn.f32x2 %0, %1, %2, %3;" : "=l"(d) : "l"(a), "l"(b), "l"(c));
    return d;
}
__device__ __forceinline__ unsigned long long pack2(float x) {
    unsigned long long d;
    asm("mov.b64 %0, {%1, %1};" : "=l"(d) : "f"(x));
    return d;
}
__device__ __forceinline__ void unpack2(unsigned long long v, float& lo, float& hi) {
    asm("mov.b64 {%0, %1}, %2;" : "=f"(lo), "=f"(hi) : "l"(v));
}
__device__ __forceinline__ void cpa16(const void* smem_dst, const void* gsrc) {
    unsigned int d = (unsigned int)__cvta_generic_to_shared(smem_dst);
    asm volatile("cp.async.cg.shared.global [%0], [%1], 16;" :: "r"(d), "l"(gsrc));
}
__device__ __forceinline__ void cpa_commit_wait() {
    asm volatile("cp.async.commit_group;");
    asm volatile("cp.async.wait_group 0;" ::: "memory");
}

// ---------------------------------------------------------------------------
// Kernel 1: qkv = n @ W_qkv.  Q,K -> g_qkv ; V -> g_vt transposed.
// ---------------------------------------------------------------------------
__global__ void __launch_bounds__(384) qkv_kernel(const float* __restrict__ nin,
                                                  const float* __restrict__ Wqkv)
{
    __shared__ float sA[8*128];
    const int tid = threadIdx.x;
    const int r0  = blockIdx.x * 8;
    for (int i = tid; i < 1024; i += 384) sA[i] = nin[(size_t)r0*128 + i];
    __syncthreads();
    float acc[8] = {0,0,0,0,0,0,0,0};
    const int c = tid;
#pragma unroll 4
    for (int d = 0; d < 128; d++) {
        const float wv = Wqkv[d*384 + c];
#pragma unroll
        for (int r = 0; r < 8; r++) acc[r] += sA[r*128 + d] * wv;
    }
    const int b = r0 >> 9;
#pragma unroll
    for (int r = 0; r < 8; r++) {
        const int tok = r0 + r;
        if (c < 256) g_qkv[(size_t)tok*384 + c] = acc[r];
        else         g_vt[(size_t)(b*128 + (c - 256))*NN + (tok & 511)] = acc[r];
    }
}

// ---------------------------------------------------------------------------
// Kernel 2: scores = clip(Q.K * DK^-0.5) -> g_Ebuf[bn][m][h]; zero g_gsum.
// ---------------------------------------------------------------------------
__global__ void __launch_bounds__(256) scores_kernel()
{
    __shared__ __align__(16) float sK[64*132];
    __shared__ __align__(16) float sQ[4*132];
    const int tid = threadIdx.x;
    const int bn0 = blockIdx.x * 4;
    const int b   = bn0 >> 9, n0 = bn0 & 511;

    if (tid < 32) {
        const int nl = tid >> 3, h = tid & 7;
        g_gsum[(b*8 + h)*NN + n0 + nl] = 0.f;
    }
    if (tid < 128) {
        const int nl = tid >> 5, c = tid & 31;
        ((float4*)sQ)[nl*33 + c] = *((const float4*)(g_qkv + (size_t)(bn0+nl)*384) + c);
    }

    const int h  = tid & 7;
    const int ml = tid >> 3;
    float4* sK4 = (float4*)sK;
    const float4* sQ4 = (const float4*)sQ;

    for (int chunk = 0; chunk < 8; chunk++) {
        const int mb = chunk * 64;
        __syncthreads();
#pragma unroll
        for (int it = 0; it < 8; it++) {
            const int i = it*256 + tid;
            const int rr = i >> 5, c = i & 31;
            sK4[rr*33 + c] =
                *((const float4*)(g_qkv + ((size_t)(b*NN + mb + rr)*384 + 128)) + c);
        }
        __syncthreads();
#pragma unroll
        for (int mm = 0; mm < 2; mm++) {
            const int m = ml + mm*32;
            const float4 k0 = sK4[m*33 + h*4 + 0];
            const float4 k1 = sK4[m*33 + h*4 + 1];
            const float4 k2 = sK4[m*33 + h*4 + 2];
            const float4 k3 = sK4[m*33 + h*4 + 3];
#pragma unroll
            for (int nl = 0; nl < 4; nl++) {
                const float4 q0 = sQ4[nl*33 + h*4 + 0];
                const float4 q1 = sQ4[nl*33 + h*4 + 1];
                const float4 q2 = sQ4[nl*33 + h*4 + 2];
                const float4 q3 = sQ4[nl*33 + h*4 + 3];
                float d = q0.x*k0.x + q0.y*k0.y + q0.z*k0.z + q0.w*k0.w
                        + q1.x*k1.x + q1.y*k1.y + q1.z*k1.z + q1.w*k1.w
                        + q2.x*k2.x + q2.y*k2.y + q2.z*k2.z + q2.w*k2.w
                        + q3.x*k3.x + q3.y*k3.y + q3.z*k3.z + q3.w*k3.w;
                d = fminf(fmaxf(d * 0.25f, -5.f), 5.f);
                g_Ebuf[((size_t)(bn0+nl)*NN + mb + m)*8 + h] = d;
            }
        }
    }
}

// ---------------------------------------------------------------------------
// Kernel 3: fused edge pass.  64 e-rows per block, 256 threads: lane QUAD per
// row (q = lane&3 owns k-slice of 32; r = w*8 + lane>>2).
//   Phase1: EG projection (f32x2) + precomputed score -> _E (g_Ebuf), G sums.
//   Phase2: e_out row = _E @ O_e into warp-private smem rows, then coalesced
//   streaming store.  e tile staged via cp.async (non-blocking).
// ---------------------------------------------------------------------------
__global__ void __launch_bounds__(256) edge_kernel(const float* __restrict__ e,
                                                   const float* __restrict__ Wg,
                                                   const float* __restrict__ We,
                                                   const float* __restrict__ Oe,
                                                   float* __restrict__ eout)
{
    __shared__ __align__(16) float sE  [64*132];   // e tile -> reused for e_out
    __shared__ __align__(16) float sWEG[128*16];   // [k][ We(8) | Wg(8) ]
    __shared__ __align__(16) float sOe [1024];     // [h][128]
    __shared__ float sGs[8];

    const int tid   = threadIdx.x;
    const int bid   = blockIdx.x;
    const int bn    = bid >> 3;
    const int mbase = (bid & 7) * 64;
    const size_t rowbase = (size_t)bn * NN + mbase;

    // --- stage e tile via cp.async (2048 float4, 8 per thread) ---
    {
        const float4* esrc = (const float4*)(e + rowbase * DDIM);
        float4* sE4 = (float4*)sE;
#pragma unroll
        for (int it = 0; it < 8; it++) {
            const int i = it*256 + tid;
            const int r = i >> 5, c = i & 31;
            cpa16(&sE4[r*33 + c], esrc + i);
        }
    }
    // weights while the bulk copy is in flight
    for (int i = tid; i < 1024; i += 256) {
        const int d = i >> 3, h = i & 7;
        sWEG[d*16 + h]     = We[i];
        sWEG[d*16 + 8 + h] = Wg[i];
        sOe[i] = Oe[i];
    }
    if (tid < 8) sGs[tid] = 0.f;
    cpa_commit_wait();
    __syncthreads();

    const int lane = tid & 31, w = tid >> 5;
    const int q = lane & 3;                  // k-slice [q*32, q*32+32)
    const int r = w*8 + (lane >> 2);         // row within tile (one per quad)
    const size_t R = rowbase + r;

    // --- phase 1: EG projection over this lane's 32 k ---
    unsigned long long aE0=0,aE1=0,aE2=0,aE3=0,aG0=0,aG1=0,aG2=0,aG3=0;
    {
        const float4* ep = (const float4*)sE + r*33 + q*8;
        const ulonglong2* wu = (const ulonglong2*)sWEG + q*128;  // 4 u2 per k
#pragma unroll
        for (int k4 = 0; k4 < 8; k4++) {
            const float4 ev = ep[k4];
            const float ev4[4] = {ev.x, ev.y, ev.z, ev.w};
#pragma unroll
            for (int j = 0; j < 4; j++) {
                const unsigned long long e2 = pack2(ev4[j]);
                const ulonglong2* wk = wu + (k4*4 + j)*4;
                const ulonglong2 wa = wk[0], wb = wk[1], wc = wk[2], wd = wk[3];
                aE0 = fma2(e2, wa.x, aE0); aE1 = fma2(e2, wa.y, aE1);
                aE2 = fma2(e2, wb.x, aE2); aE3 = fma2(e2, wb.y, aE3);
                aG0 = fma2(e2, wc.x, aG0); aG1 = fma2(e2, wc.y, aG1);
                aG2 = fma2(e2, wd.x, aG2); aG3 = fma2(e2, wd.y, aG3);
            }
        }
    }
    float accE[8], accG[8];
    unpack2(aE0, accE[0], accE[1]); unpack2(aE1, accE[2], accE[3]);
    unpack2(aE2, accE[4], accE[5]); unpack2(aE3, accE[6], accE[7]);
    unpack2(aG0, accG[0], accG[1]); unpack2(aG1, accG[2], accG[3]);
    unpack2(aG2, accG[4], accG[5]); unpack2(aG3, accG[6], accG[7]);
    // reduce over the 4 quad lanes: every quad lane ends with full sums
#pragma unroll
    for (int h = 0; h < 8; h++) {
        accE[h] += __shfl_xor_sync(0xffffffffu, accE[h], 1);
        accE[h] += __shfl_xor_sync(0xffffffffu, accE[h], 2);
        accG[h] += __shfl_xor_sync(0xffffffffu, accG[h], 1);
        accG[h] += __shfl_xor_sync(0xffffffffu, accG[h], 2);
    }

    // add precomputed clipped score -> _E
    float Ef[8];
    {
        const float4* sp = (const float4*)(g_Ebuf + R*8);
        const float4 s0 = sp[0], s1 = sp[1];
        Ef[0]=accE[0]+s0.x; Ef[1]=accE[1]+s0.y; Ef[2]=accE[2]+s0.z; Ef[3]=accE[3]+s0.w;
        Ef[4]=accE[4]+s1.x; Ef[5]=accE[5]+s1.y; Ef[6]=accE[6]+s1.z; Ef[7]=accE[7]+s1.w;
    }
    if (q == 0) {   // write back _E for the attention kernel
        float4* dp = (float4*)(g_Ebuf + R*8);
        dp[0] = make_float4(Ef[0], Ef[1], Ef[2], Ef[3]);
        dp[1] = make_float4(Ef[4], Ef[5], Ef[6], Ef[7]);
    }

    // G sigmoid sums: values identical across the quad, so xor 4/8/16 stays
    // within the q-class and sums the warp's 8 rows without masking.
#pragma unroll
    for (int h = 0; h < 8; h++) {
        float sg = 1.f / (1.f + __expf(-accG[h]));
        sg += __shfl_xor_sync(0xffffffffu, sg, 4);
        sg += __shfl_xor_sync(0xffffffffu, sg, 8);
        sg += __shfl_xor_sync(0xffffffffu, sg, 16);
        if (lane == 0) atomicAdd(&sGs[h], sg);
    }

    // --- phase 2: e_out row (rank-8), lane covers cols [q*32, q*32+32) ---
    {
        unsigned long long efp[8];
#pragma unroll
        for (int h = 0; h < 8; h++) efp[h] = pack2(Ef[h]);
        const ulonglong2* oeu = (const ulonglong2*)sOe;   // 32 u2 per head
        ulonglong2* orow = (ulonglong2*)(sE + r*132);
#pragma unroll
        for (int c = 0; c < 8; c++) {
            unsigned long long ax = 0ull, ay = 0ull;
#pragma unroll
            for (int h = 0; h < 8; h++) {
                const ulonglong2 ov = oeu[h*32 + q*8 + c];
                ax = fma2(efp[h], ov.x, ax);
                ay = fma2(efp[h], ov.y, ay);
            }
            ulonglong2 st; st.x = ax; st.y = ay;
            orow[q*8 + c] = st;
        }
    }
    __syncwarp();
    {   // coalesced streaming store of this warp's 8 rows
        const int wbase = w * 8;
        const float4* sE4 = (const float4*)sE;
        float4* dst = (float4*)eout + (rowbase + wbase)*32;
#pragma unroll
        for (int rr = 0; rr < 8; rr++) {
            const float4 v = sE4[(wbase + rr)*33 + lane];
            __stcs(dst + rr*32 + lane, v);
        }
    }
    __syncthreads();
    if (tid < 8) {
        const int b = bn >> 9, n = bn & 511;
        atomicAdd(&g_gsum[(b*8 + tid)*NN + n], sGs[tid]);
    }
}

// ---------------------------------------------------------------------------
// Kernel 4: softmax(_E) @ V (transposed layout) * log1p(Gsum), then fused
// n_out = n_mid @ O_n.  Block per (b,n), warp per head.
// ---------------------------------------------------------------------------
__global__ void __launch_bounds__(256) attn_kernel(const float* __restrict__ On,
                                                   float* __restrict__ out)
{
    __shared__ float sE[8*520];
    __shared__ float nmid[128];
    __shared__ float pacc[128];
    const int tid = threadIdx.x, bn = blockIdx.x;
    const int b = bn >> 9, n = bn & 511;

    const float4* Eb = (const float4*)(g_Ebuf + (size_t)bn*4096);
    for (int i = tid; i < 1024; i += 256) {
        const float4 v = Eb[i];
        const int m = i >> 1, h0 = (i & 1) * 4;
        sE[(h0+0)*520 + m] = v.x;
        sE[(h0+1)*520 + m] = v.y;
        sE[(h0+2)*520 + m] = v.z;
        sE[(h0+3)*520 + m] = v.w;
    }
    __syncthreads();

    const int h = tid >> 5, lane = tid & 31;
    float x[16];
#pragma unroll
    for (int k = 0; k < 16; k++) x[k] = sE[h*520 + lane + k*32];

    float mx = x[0];
#pragma unroll
    for (int k = 1; k < 16; k++) mx = fmaxf(mx, x[k]);
#pragma unroll
    for (int off = 16; off > 0; off >>= 1)
        mx = fmaxf(mx, __shfl_xor_sync(0xffffffffu, mx, off));

    float p[16]; float s = 0.f;
#pragma unroll
    for (int k = 0; k < 16; k++) { p[k] = __expf(x[k] - mx); s += p[k]; }
#pragma unroll
    for (int off = 16; off > 0; off >>= 1)
        s += __shfl_xor_sync(0xffffffffu, s, off);

    // A @ V with transposed V: contiguous loads per (h,d)
    const float* vb = g_vt + (size_t)(b*128 + h*16)*NN + lane;
    float o[16];
#pragma unroll
    for (int d = 0; d < 16; d++) {
        const float* vr = vb + d*NN;
        float a = 0.f;
#pragma unroll
        for (int k = 0; k < 16; k++) a += p[k] * vr[k*32];
        o[d] = a;
    }
#pragma unroll
    for (int off = 16; off > 0; off >>= 1) {
#pragma unroll
        for (int d = 0; d < 16; d++)
            o[d] += __shfl_xor_sync(0xffffffffu, o[d], off);
    }
    if (lane == 0) {
        const float dc = log1pf(g_gsum[(b*8 + h)*NN + n]);
        const float sc = dc / s;
#pragma unroll
        for (int d = 0; d < 16; d++) nmid[h*16 + d] = o[d] * sc;
    }
    __syncthreads();

    // fused n_out = n_mid @ O_n (two half-dots per column)
    const int c = tid & 127, part = tid >> 7;
    float a = 0.f;
    const float* onp = On + (size_t)(part*64)*128 + c;
#pragma unroll 8
    for (int d = 0; d < 64; d++) a += nmid[part*64 + d] * onp[(size_t)d*128];
    if (part == 1) pacc[c] = a;
    __syncthreads();
    if (part == 0) out[(size_t)bn*128 + c] = a + pacc[c];
}

// ---------------------------------------------------------------------------
// Launch: inputs: n, e, W_qkv, O_n, W_g, W_e, O_e.
// Output: n_out (131072 floats) then e_out (67108864 floats).
// ---------------------------------------------------------------------------
extern "C" void kernel_launch(void* const* d_in, const int* in_sizes, int n_in,
                              void* d_out, int out_size)
{
    const float* n_in_p = (const float*)d_in[0];
    const float* e_p    = (const float*)d_in[1];
    const float* Wqkv_p = (const float*)d_in[2];
    const float* On_p   = (const float*)d_in[3];
    const float* Wg_p   = (const float*)d_in[4];
    const float* We_p   = (const float*)d_in[5];
    const float* Oe_p   = (const float*)d_in[6];
    float* out = (float*)d_out;

    qkv_kernel   <<<NB*NN/8, 384>>>(n_in_p, Wqkv_p);
    scores_kernel<<<NB*NN/4, 256>>>();
    edge_kernel  <<<NB*NN*8, 256>>>(e_p, Wg_p, We_p, Oe_p, out + NB*NN*DDIM);
    attn_kernel  <<<NB*NN,   256>>>(On_p, out);
}

// round 6
// speedup vs baseline: 3.1203x; 3.1203x over previous
#include <cuda_runtime.h>

#define NB   2
#define NN   512
#define DDIM 128
#define HH   8

// ---------------------------------------------------------------------------
// Scratch (device globals — no allocation allowed)
// ---------------------------------------------------------------------------
__device__ __align__(128) float g_qkv [NB*NN*384];          // Q at [tok][0..128), K at [128..256)
__device__ __align__(128) float g_vt  [NB*HH*16*NN];        // V transposed: [b][h][dk][m]
__device__ __align__(128) float g_Ebuf[(size_t)NB*NN*NN*HH];// scores then _E, layout [b][n][m][h]
__device__ __align__(128) float g_gsum[NB*HH*NN];           // sum_m sigmoid(G)

// ---------------------------------------------------------------------------
// Packed f32x2 helpers (Blackwell dual FP32)
// ---------------------------------------------------------------------------
__device__ __forceinline__ unsigned long long fma2(unsigned long long a,
                                                   unsigned long long b,
                                                   unsigned long long c) {
    unsigned long long d;
    asm("fma.rn.f32x2 %0, %1, %2, %3;" : "=l"(d) : "l"(a), "l"(b), "l"(c));
    return d;
}
__device__ __forceinline__ unsigned long long pack2(float x) {
    unsigned long long d;
    asm("mov.b64 %0, {%1, %1};" : "=l"(d) : "f"(x));
    return d;
}
__device__ __forceinline__ void unpack2(unsigned long long v, float& lo, float& hi) {
    asm("mov.b64 {%0, %1}, %2;" : "=f"(lo), "=f"(hi) : "l"(v));
}

// ---------------------------------------------------------------------------
// Kernel 1: qkv = n @ W_qkv.  Q,K -> g_qkv ; V -> g_vt transposed.
// ---------------------------------------------------------------------------
__global__ void __launch_bounds__(384) qkv_kernel(const float* __restrict__ nin,
                                                  const float* __restrict__ Wqkv)
{
    __shared__ float sA[8*128];
    const int tid = threadIdx.x;
    const int r0  = blockIdx.x * 8;
    for (int i = tid; i < 1024; i += 384) sA[i] = nin[(size_t)r0*128 + i];
    __syncthreads();
    float acc[8] = {0,0,0,0,0,0,0,0};
    const int c = tid;
#pragma unroll 4
    for (int d = 0; d < 128; d++) {
        const float wv = Wqkv[d*384 + c];
#pragma unroll
        for (int r = 0; r < 8; r++) acc[r] += sA[r*128 + d] * wv;
    }
    const int b = r0 >> 9;
#pragma unroll
    for (int r = 0; r < 8; r++) {
        const int tok = r0 + r;
        if (c < 256) g_qkv[(size_t)tok*384 + c] = acc[r];
        else         g_vt[(size_t)(b*128 + (c - 256))*NN + (tok & 511)] = acc[r];
    }
}

// ---------------------------------------------------------------------------
// Kernel 2: scores = clip(Q.K * DK^-0.5) -> g_Ebuf[bn][m][h]; zero g_gsum.
// ---------------------------------------------------------------------------
__global__ void __launch_bounds__(256) scores_kernel()
{
    __shared__ __align__(16) float sK[64*132];
    __shared__ __align__(16) float sQ[4*132];
    const int tid = threadIdx.x;
    const int bn0 = blockIdx.x * 4;
    const int b   = bn0 >> 9, n0 = bn0 & 511;

    if (tid < 32) {
        const int nl = tid >> 3, h = tid & 7;
        g_gsum[(b*8 + h)*NN + n0 + nl] = 0.f;
    }
    if (tid < 128) {
        const int nl = tid >> 5, c = tid & 31;
        ((float4*)sQ)[nl*33 + c] = *((const float4*)(g_qkv + (size_t)(bn0+nl)*384) + c);
    }

    const int h  = tid & 7;
    const int ml = tid >> 3;
    float4* sK4 = (float4*)sK;
    const float4* sQ4 = (const float4*)sQ;

    for (int chunk = 0; chunk < 8; chunk++) {
        const int mb = chunk * 64;
        __syncthreads();
#pragma unroll
        for (int it = 0; it < 8; it++) {
            const int i = it*256 + tid;
            const int rr = i >> 5, c = i & 31;
            sK4[rr*33 + c] =
                *((const float4*)(g_qkv + ((size_t)(b*NN + mb + rr)*384 + 128)) + c);
        }
        __syncthreads();
#pragma unroll
        for (int mm = 0; mm < 2; mm++) {
            const int m = ml + mm*32;
            const float4 k0 = sK4[m*33 + h*4 + 0];
            const float4 k1 = sK4[m*33 + h*4 + 1];
            const float4 k2 = sK4[m*33 + h*4 + 2];
            const float4 k3 = sK4[m*33 + h*4 + 3];
#pragma unroll
            for (int nl = 0; nl < 4; nl++) {
                const float4 q0 = sQ4[nl*33 + h*4 + 0];
                const float4 q1 = sQ4[nl*33 + h*4 + 1];
                const float4 q2 = sQ4[nl*33 + h*4 + 2];
                const float4 q3 = sQ4[nl*33 + h*4 + 3];
                float d = q0.x*k0.x + q0.y*k0.y + q0.z*k0.z + q0.w*k0.w
                        + q1.x*k1.x + q1.y*k1.y + q1.z*k1.z + q1.w*k1.w
                        + q2.x*k2.x + q2.y*k2.y + q2.z*k2.z + q2.w*k2.w
                        + q3.x*k3.x + q3.y*k3.y + q3.z*k3.z + q3.w*k3.w;
                d = fminf(fmaxf(d * 0.25f, -5.f), 5.f);
                g_Ebuf[((size_t)(bn0+nl)*NN + mb + m)*8 + h] = d;
            }
        }
    }
}

// ---------------------------------------------------------------------------
// Kernel 3: fused edge pass.  64 e-rows per block, 256 threads = 8 warps.
// e tile staged K-MAJOR (sET[k][row], stride 65 => conflict-free).
// Phase 1: warp = (row-half hf, k-slice sl of 32); lane = row. Weight reads are
//   UNIFORM (broadcast), e reads conflict-free LDS.32. Output-pair FFMA2.
// Cross-warp k reduction via sET region (stride 69, odd => conflict-free).
// Phase 2: warp = (row-half, col-slice of 32); lane = row. Oe reads UNIFORM
//   broadcast; e_out stored directly with st.cs float4.
// ---------------------------------------------------------------------------
__global__ void __launch_bounds__(256) edge_kernel(const float* __restrict__ e,
                                                   const float* __restrict__ Wg,
                                                   const float* __restrict__ We,
                                                   const float* __restrict__ Oe,
                                                   float* __restrict__ eout)
{
    __shared__ __align__(16) float sET[128*65];   // k-major e tile; reused for partials
    __shared__ __align__(16) float sW [128*16];   // [k][ We(8) | Wg(8) ]
    __shared__ __align__(16) float sOe[8*128];    // [h][c]
    __shared__ float sGs[8];

    const int tid   = threadIdx.x;
    const int bid   = blockIdx.x;
    const int bn    = bid >> 3;
    const int mbase = (bid & 7) * 64;
    const size_t rowbase = (size_t)bn * NN + mbase;
    const int lane = tid & 31, w = tid >> 5;

    // weights + Oe into smem
    for (int i = tid; i < 1024; i += 256) {
        const int d = i >> 3, h = i & 7;
        sW[d*16 + h]     = We[i];     // i = d*8+h
        sW[d*16 + 8 + h] = Wg[i];
        sOe[i] = Oe[i];               // [h][c]
    }
    if (tid < 8) sGs[tid] = 0.f;

    // --- stage e tile transposed: lane = k-column, warp stages 8 rows ---
    {
        const float* ebase = e + rowbase * DDIM + w*8*DDIM + lane;
        float v[32];
#pragma unroll
        for (int rr = 0; rr < 8; rr++)
#pragma unroll
            for (int c = 0; c < 4; c++)
                v[rr*4 + c] = __ldcs(ebase + rr*DDIM + 32*c);
#pragma unroll
        for (int rr = 0; rr < 8; rr++)
#pragma unroll
            for (int c = 0; c < 4; c++)
                sET[(lane + 32*c)*65 + (w*8 + rr)] = v[rr*4 + c];
    }
    __syncthreads();

    const int hf = w & 1;            // row half
    const int sl = w >> 1;           // k-slice (phase1) / col-slice (phase2)
    const int r  = hf*32 + lane;     // my row within tile
    const size_t R = rowbase + r;

    // --- phase 1: E/G partial projection over k-slice [sl*32, sl*32+32) ---
    unsigned long long acc[8] = {0,0,0,0,0,0,0,0};
    {
        const float* ep = sET + sl*32*65 + r;
        const ulonglong2* wp = (const ulonglong2*)sW + sl*32*4;
#pragma unroll 8
        for (int kk = 0; kk < 32; kk++) {
            const unsigned long long e2 = pack2(ep[kk*65]);
            const ulonglong2 wa = wp[kk*4+0], wb = wp[kk*4+1];
            const ulonglong2 wc = wp[kk*4+2], wd = wp[kk*4+3];
            acc[0] = fma2(e2, wa.x, acc[0]); acc[1] = fma2(e2, wa.y, acc[1]);
            acc[2] = fma2(e2, wb.x, acc[2]); acc[3] = fma2(e2, wb.y, acc[3]);
            acc[4] = fma2(e2, wc.x, acc[4]); acc[5] = fma2(e2, wc.y, acc[5]);
            acc[6] = fma2(e2, wd.x, acc[6]); acc[7] = fma2(e2, wd.y, acc[7]);
        }
    }
    __syncthreads();   // sET reads done everywhere; safe to reuse as partials

    {   // write partials: sP[row][slice][16], row stride 69 (odd -> no conflicts)
        float pf[16];
#pragma unroll
        for (int j = 0; j < 8; j++) unpack2(acc[j], pf[2*j], pf[2*j+1]);
        float* pr = sET + r*69 + sl*16;
#pragma unroll
        for (int i = 0; i < 16; i++) pr[i] = pf[i];
    }
    __syncthreads();

    // --- reduce k-slices + scores ---
    float Ef[8], G[8];
    {
        const float* pr = sET + r*69;
#pragma unroll
        for (int h = 0; h < 8; h++) {
            Ef[h] = pr[h] + pr[16+h] + pr[32+h] + pr[48+h];
            G[h]  = pr[8+h] + pr[24+h] + pr[40+h] + pr[56+h];
        }
        const float4* sp = (const float4*)(g_Ebuf + R*8);
        const float4 s0 = sp[0], s1 = sp[1];
        Ef[0]+=s0.x; Ef[1]+=s0.y; Ef[2]+=s0.z; Ef[3]+=s0.w;
        Ef[4]+=s1.x; Ef[5]+=s1.y; Ef[6]+=s1.z; Ef[7]+=s1.w;
    }
    if (sl == 0) {
        // write back _E for attention (coalesced: lanes cover 1KB)
        float4* dp = (float4*)(g_Ebuf + R*8);
        dp[0] = make_float4(Ef[0], Ef[1], Ef[2], Ef[3]);
        dp[1] = make_float4(Ef[4], Ef[5], Ef[6], Ef[7]);
        // G sigmoid sums across the 32 rows of this warp
#pragma unroll
        for (int h = 0; h < 8; h++) {
            float sg = 1.f / (1.f + __expf(-G[h]));
            sg += __shfl_xor_sync(0xffffffffu, sg, 1);
            sg += __shfl_xor_sync(0xffffffffu, sg, 2);
            sg += __shfl_xor_sync(0xffffffffu, sg, 4);
            sg += __shfl_xor_sync(0xffffffffu, sg, 8);
            sg += __shfl_xor_sync(0xffffffffu, sg, 16);
            if (lane == 0) atomicAdd(&sGs[h], sg);
        }
    }

    // --- phase 2: e_out row slice [sl*32, sl*32+32) = _E . O_e, direct st.cs ---
    {
        unsigned long long efp[8];
#pragma unroll
        for (int h = 0; h < 8; h++) efp[h] = pack2(Ef[h]);
        const ulonglong2* oeu = (const ulonglong2*)sOe;  // 32 u2 per head row
        float* outp = eout + R*DDIM + sl*32;
#pragma unroll
        for (int cc = 0; cc < 8; cc++) {
            unsigned long long ax = 0ull, ay = 0ull;
#pragma unroll
            for (int h = 0; h < 8; h++) {
                const ulonglong2 ov = oeu[h*32 + sl*8 + cc];  // uniform per warp
                ax = fma2(efp[h], ov.x, ax);
                ay = fma2(efp[h], ov.y, ay);
            }
            float o0, o1, o2, o3;
            unpack2(ax, o0, o1); unpack2(ay, o2, o3);
            __stcs((float4*)(outp + cc*4), make_float4(o0, o1, o2, o3));
        }
    }

    __syncthreads();
    if (tid < 8) {
        const int b = bn >> 9, n = bn & 511;
        atomicAdd(&g_gsum[(b*8 + tid)*NN + n], sGs[tid]);
    }
}

// ---------------------------------------------------------------------------
// Kernel 4: softmax(_E) @ V (transposed layout) * log1p(Gsum), then fused
// n_out = n_mid @ O_n.  Block per (b,n), warp per head.
// ---------------------------------------------------------------------------
__global__ void __launch_bounds__(256) attn_kernel(const float* __restrict__ On,
                                                   float* __restrict__ out)
{
    __shared__ float sE[8*520];
    __shared__ float nmid[128];
    __shared__ float pacc[128];
    const int tid = threadIdx.x, bn = blockIdx.x;
    const int b = bn >> 9, n = bn & 511;

    const float4* Eb = (const float4*)(g_Ebuf + (size_t)bn*4096);
    for (int i = tid; i < 1024; i += 256) {
        const float4 v = Eb[i];
        const int m = i >> 1, h0 = (i & 1) * 4;
        sE[(h0+0)*520 + m] = v.x;
        sE[(h0+1)*520 + m] = v.y;
        sE[(h0+2)*520 + m] = v.z;
        sE[(h0+3)*520 + m] = v.w;
    }
    __syncthreads();

    const int h = tid >> 5, lane = tid & 31;
    float x[16];
#pragma unroll
    for (int k = 0; k < 16; k++) x[k] = sE[h*520 + lane + k*32];

    float mx = x[0];
#pragma unroll
    for (int k = 1; k < 16; k++) mx = fmaxf(mx, x[k]);
#pragma unroll
    for (int off = 16; off > 0; off >>= 1)
        mx = fmaxf(mx, __shfl_xor_sync(0xffffffffu, mx, off));

    float p[16]; float s = 0.f;
#pragma unroll
    for (int k = 0; k < 16; k++) { p[k] = __expf(x[k] - mx); s += p[k]; }
#pragma unroll
    for (int off = 16; off > 0; off >>= 1)
        s += __shfl_xor_sync(0xffffffffu, s, off);

    const float* vb = g_vt + (size_t)(b*128 + h*16)*NN + lane;
    float o[16];
#pragma unroll
    for (int d = 0; d < 16; d++) {
        const float* vr = vb + d*NN;
        float a = 0.f;
#pragma unroll
        for (int k = 0; k < 16; k++) a += p[k] * vr[k*32];
        o[d] = a;
    }
#pragma unroll
    for (int off = 16; off > 0; off >>= 1) {
#pragma unroll
        for (int d = 0; d < 16; d++)
            o[d] += __shfl_xor_sync(0xffffffffu, o[d], off);
    }
    if (lane == 0) {
        const float dc = log1pf(g_gsum[(b*8 + h)*NN + n]);
        const float sc = dc / s;
#pragma unroll
        for (int d = 0; d < 16; d++) nmid[h*16 + d] = o[d] * sc;
    }
    __syncthreads();

    const int c = tid & 127, part = tid >> 7;
    float a = 0.f;
    const float* onp = On + (size_t)(part*64)*128 + c;
#pragma unroll 8
    for (int d = 0; d < 64; d++) a += nmid[part*64 + d] * onp[(size_t)d*128];
    if (part == 1) pacc[c] = a;
    __syncthreads();
    if (part == 0) out[(size_t)bn*128 + c] = a + pacc[c];
}

// ---------------------------------------------------------------------------
// Launch: inputs: n, e, W_qkv, O_n, W_g, W_e, O_e.
// Output: n_out (131072 floats) then e_out (67108864 floats).
// ---------------------------------------------------------------------------
extern "C" void kernel_launch(void* const* d_in, const int* in_sizes, int n_in,
                              void* d_out, int out_size)
{
    const float* n_in_p = (const float*)d_in[0];
    const float* e_p    = (const float*)d_in[1];
    const float* Wqkv_p = (const float*)d_in[2];
    const float* On_p   = (const float*)d_in[3];
    const float* Wg_p   = (const float*)d_in[4];
    const float* We_p   = (const float*)d_in[5];
    const float* Oe_p   = (const float*)d_in[6];
    float* out = (float*)d_out;

    qkv_kernel   <<<NB*NN/8, 384>>>(n_in_p, Wqkv_p);
    scores_kernel<<<NB*NN/4, 256>>>();
    edge_kernel  <<<NB*NN*8, 256>>>(e_p, Wg_p, We_p, Oe_p, out + NB*NN*DDIM);
    attn_kernel  <<<NB*NN,   256>>>(On_p, out);
}